// round 1
// baseline (speedup 1.0000x reference)
#include <cuda_runtime.h>
#include <math.h>

#define Nn 50000
#define Ee 400000
#define Dd 128
#define Hh 4
#define DHh 32
#define Tt 3
#define Rr 6
#define Ll 2

// ---------------- scratch (static device globals; no runtime alloc) ----------------
__device__ float g_k[Nn * Dd];
__device__ float g_q[Nn * Dd];
__device__ float g_v[Nn * Dd];
__device__ float g_ex[Ee * Hh];
__device__ float g_den[Nn * Hh];
__device__ float g_agg[Nn * Dd];
__device__ float g_ha[Nn * Dd];
__device__ float g_out0[Nn * Dd];
__device__ float g_out1[Nn * Dd];

// ---------------- typed per-node GEMM: Out[n,:] = X[n,:] @ W[ntype[n]] ----------------
// W points at [T][128][128] for one (layer, matrix). ntype is sorted -> almost all
// 64-row tiles are single-type; mixed tiles (<=2 per launch) take <=3 passes.
__global__ void typed_gemm(const float* __restrict__ X, const float* __restrict__ W,
                           const int* __restrict__ ntype, float* __restrict__ Out) {
    __shared__ float Xs[64 * 128];
    __shared__ int ts[64];
    const int r0 = blockIdx.x * 64;
    const int tid = threadIdx.x;

    // load X tile (64 rows x 128 cols) as float4
    for (int i = tid; i < 2048; i += 256) {
        int row = r0 + (i >> 5);
        float4 val = make_float4(0.f, 0.f, 0.f, 0.f);
        if (row < Nn) val = ((const float4*)X)[row * 32 + (i & 31)];
        ((float4*)Xs)[i] = val;
    }
    for (int i = tid; i < 64; i += 256) {
        int row = r0 + i;
        ts[i] = (row < Nn) ? ntype[row] : ntype[Nn - 1];
    }
    __syncthreads();

    const int nrows = (Nn - r0 < 64) ? (Nn - r0) : 64;
    const int t0 = ts[0], t1 = ts[nrows - 1];
    const int tx = tid & 31;   // 4 output cols each -> 128 cols
    const int ty = tid >> 5;   // 8 row-groups of 8 rows

    for (int t = t0; t <= t1; ++t) {
        const float* Wt = W + t * 16384;
        float acc[8][4];
#pragma unroll
        for (int j = 0; j < 8; ++j) {
            acc[j][0] = 0.f; acc[j][1] = 0.f; acc[j][2] = 0.f; acc[j][3] = 0.f;
        }
#pragma unroll 4
        for (int k = 0; k < 128; ++k) {
            float4 w4 = ((const float4*)(Wt + k * 128))[tx];
#pragma unroll
            for (int j = 0; j < 8; ++j) {
                float xv = Xs[(ty * 8 + j) * 128 + k];
                acc[j][0] += xv * w4.x;
                acc[j][1] += xv * w4.y;
                acc[j][2] += xv * w4.z;
                acc[j][3] += xv * w4.w;
            }
        }
#pragma unroll
        for (int j = 0; j < 8; ++j) {
            int lr = ty * 8 + j;
            int row = r0 + lr;
            if (row < Nn && ts[lr] == t) {
                float4 o;
                o.x = acc[j][0]; o.y = acc[j][1]; o.z = acc[j][2]; o.w = acc[j][3];
                ((float4*)Out)[row * 32 + tx] = o;
            }
        }
    }
}

// ---------------- edge scores: ex[e,h] = exp( (k_src W_att[h,r]) . q_dst * pri / sqrt(DH) )
// plus den[dst,h] += ex. Warp per edge; all W_att (96KB) cached in dynamic smem.
__global__ void edge_score(const float* __restrict__ kk, const float* __restrict__ qq,
                           const int* __restrict__ src, const int* __restrict__ dst,
                           const int* __restrict__ etype,
                           const float* __restrict__ Watt, const float* __restrict__ pri,
                           float* __restrict__ ex, float* __restrict__ den) {
    extern __shared__ float Ws[];   // H*R*32*32 = 24576 floats
    __shared__ float Pri[Hh * Rr];
    for (int i = threadIdx.x; i < Hh * Rr * DHh * DHh; i += blockDim.x) Ws[i] = Watt[i];
    if (threadIdx.x < Hh * Rr) Pri[threadIdx.x] = pri[threadIdx.x];
    __syncthreads();

    const int lane = threadIdx.x & 31;
    const int warp = blockIdx.x * (blockDim.x >> 5) + (threadIdx.x >> 5);
    const int nwarp = gridDim.x * (blockDim.x >> 5);

    for (int e = warp; e < Ee; e += nwarp) {
        int s = src[e], dn = dst[e], r = etype[e];
#pragma unroll
        for (int h = 0; h < Hh; ++h) {
            float kv = kk[s * Dd + h * DHh + lane];
            float qv = qq[dn * Dd + h * DHh + lane];
            const float* w = Ws + (h * Rr + r) * (DHh * DHh);
            float acc = 0.f;
#pragma unroll
            for (int d = 0; d < 32; ++d)
                acc += __shfl_sync(0xffffffffu, kv, d) * w[d * 32 + lane];
            float p = acc * qv;
#pragma unroll
            for (int off = 16; off > 0; off >>= 1)
                p += __shfl_xor_sync(0xffffffffu, p, off);
            if (lane == 0) {
                float a = p * Pri[h * Rr + r] * 0.17677669529663687f;  // 1/sqrt(32)
                float ev = expf(a);
                ex[e * Hh + h] = ev;
                atomicAdd(&den[dn * Hh + h], ev);
            }
        }
    }
}

// ---------------- edge aggregate: agg[dst] += (ex/den[dst]) * (v_src W_msg[h,r]) ----------------
__global__ void edge_agg(const float* __restrict__ vv, const int* __restrict__ src,
                         const int* __restrict__ dst, const int* __restrict__ etype,
                         const float* __restrict__ Wmsg,
                         const float* __restrict__ ex, const float* __restrict__ den,
                         float* __restrict__ agg) {
    extern __shared__ float Ws[];
    for (int i = threadIdx.x; i < Hh * Rr * DHh * DHh; i += blockDim.x) Ws[i] = Wmsg[i];
    __syncthreads();

    const int lane = threadIdx.x & 31;
    const int warp = blockIdx.x * (blockDim.x >> 5) + (threadIdx.x >> 5);
    const int nwarp = gridDim.x * (blockDim.x >> 5);

    for (int e = warp; e < Ee; e += nwarp) {
        int s = src[e], dn = dst[e], r = etype[e];
#pragma unroll
        for (int h = 0; h < Hh; ++h) {
            float att = ex[e * Hh + h] / den[dn * Hh + h];
            float vval = vv[s * Dd + h * DHh + lane];
            const float* w = Ws + (h * Rr + r) * (DHh * DHh);
            float acc = 0.f;
#pragma unroll
            for (int d = 0; d < 32; ++d)
                acc += __shfl_sync(0xffffffffu, vval, d) * w[d * 32 + lane];
            atomicAdd(&agg[dn * Dd + h * DHh + lane], att * acc);
        }
    }
}

// ---------------- per-node: pre = x*(2-sk) + h_a*sk ; out = LN(pre) ----------------
// warp per row (N = 50000 = 6250 blocks * 8 warps exactly)
__global__ void node_epilogue(const float* __restrict__ X, const float* __restrict__ Ha,
                              const int* __restrict__ ntype,
                              const float* __restrict__ skip,
                              const float* __restrict__ lng, const float* __restrict__ lnb,
                              float* __restrict__ OutL) {
    const int lane = threadIdx.x & 31;
    const int row = blockIdx.x * (blockDim.x >> 5) + (threadIdx.x >> 5);
    if (row >= Nn) return;
    int t = ntype[row];
    float sk = 1.f / (1.f + expf(-skip[t]));

    float4 x4 = ((const float4*)X)[row * 32 + lane];
    float4 h4 = ((const float4*)Ha)[row * 32 + lane];
    float p0 = x4.x * (2.f - sk) + h4.x * sk;
    float p1 = x4.y * (2.f - sk) + h4.y * sk;
    float p2 = x4.z * (2.f - sk) + h4.z * sk;
    float p3 = x4.w * (2.f - sk) + h4.w * sk;

    float s = p0 + p1 + p2 + p3;
#pragma unroll
    for (int off = 16; off > 0; off >>= 1) s += __shfl_xor_sync(0xffffffffu, s, off);
    float mu = s * (1.f / 128.f);
    float d0 = p0 - mu, d1 = p1 - mu, d2 = p2 - mu, d3 = p3 - mu;
    float qv = d0 * d0 + d1 * d1 + d2 * d2 + d3 * d3;
#pragma unroll
    for (int off = 16; off > 0; off >>= 1) qv += __shfl_xor_sync(0xffffffffu, qv, off);
    float inv = rsqrtf(qv * (1.f / 128.f) + 1e-5f);

    float4 g4 = ((const float4*)lng)[lane];
    float4 b4 = ((const float4*)lnb)[lane];
    float4 o;
    o.x = d0 * inv * g4.x + b4.x;
    o.y = d1 * inv * g4.y + b4.y;
    o.z = d2 * inv * g4.z + b4.z;
    o.w = d3 * inv * g4.w + b4.w;
    ((float4*)OutL)[row * 32 + lane] = o;
}

// ---------------- final: mixed = softmax(agg_w) . outs ; out = LN(mixed) ----------------
__global__ void final_mix(const float* __restrict__ o0, const float* __restrict__ o1,
                          const float* __restrict__ aw,
                          const float* __restrict__ gg, const float* __restrict__ bb,
                          float* __restrict__ out) {
    const int lane = threadIdx.x & 31;
    const int row = blockIdx.x * (blockDim.x >> 5) + (threadIdx.x >> 5);
    if (row >= Nn) return;
    float e0 = expf(aw[0]), e1 = expf(aw[1]);
    float w0 = e0 / (e0 + e1), w1 = e1 / (e0 + e1);

    float4 a4 = ((const float4*)o0)[row * 32 + lane];
    float4 c4 = ((const float4*)o1)[row * 32 + lane];
    float p0 = w0 * a4.x + w1 * c4.x;
    float p1 = w0 * a4.y + w1 * c4.y;
    float p2 = w0 * a4.z + w1 * c4.z;
    float p3 = w0 * a4.w + w1 * c4.w;

    float s = p0 + p1 + p2 + p3;
#pragma unroll
    for (int off = 16; off > 0; off >>= 1) s += __shfl_xor_sync(0xffffffffu, s, off);
    float mu = s * (1.f / 128.f);
    float d0 = p0 - mu, d1 = p1 - mu, d2 = p2 - mu, d3 = p3 - mu;
    float qv = d0 * d0 + d1 * d1 + d2 * d2 + d3 * d3;
#pragma unroll
    for (int off = 16; off > 0; off >>= 1) qv += __shfl_xor_sync(0xffffffffu, qv, off);
    float inv = rsqrtf(qv * (1.f / 128.f) + 1e-5f);

    float4 g4 = ((const float4*)gg)[lane];
    float4 b4 = ((const float4*)bb)[lane];
    float4 o;
    o.x = d0 * inv * g4.x + b4.x;
    o.y = d1 * inv * g4.y + b4.y;
    o.z = d2 * inv * g4.z + b4.z;
    o.w = d3 * inv * g4.w + b4.w;
    ((float4*)out)[row * 32 + lane] = o;
}

extern "C" void kernel_launch(void* const* d_in, const int* in_sizes, int n_in,
                              void* d_out, int out_size) {
    (void)in_sizes; (void)n_in; (void)out_size;
    const float* h     = (const float*)d_in[0];
    const int*   src   = (const int*)d_in[1];
    const int*   dst   = (const int*)d_in[2];
    const int*   ntype = (const int*)d_in[3];
    const int*   etype = (const int*)d_in[4];
    const float* Wk    = (const float*)d_in[5];
    const float* Wq    = (const float*)d_in[6];
    const float* Wv    = (const float*)d_in[7];
    const float* Wa    = (const float*)d_in[8];
    const float* Watt  = (const float*)d_in[9];
    const float* Wmsg  = (const float*)d_in[10];
    const float* pri   = (const float*)d_in[11];
    const float* skip  = (const float*)d_in[12];
    const float* lng   = (const float*)d_in[13];
    const float* lnb   = (const float*)d_in[14];
    const float* aggw  = (const float*)d_in[15];
    const float* aggg  = (const float*)d_in[16];
    const float* aggb  = (const float*)d_in[17];
    float* out = (float*)d_out;

    float *pk, *pq, *pv, *pex, *pden, *pagg, *pha, *po0, *po1;
    cudaGetSymbolAddress((void**)&pk,   g_k);
    cudaGetSymbolAddress((void**)&pq,   g_q);
    cudaGetSymbolAddress((void**)&pv,   g_v);
    cudaGetSymbolAddress((void**)&pex,  g_ex);
    cudaGetSymbolAddress((void**)&pden, g_den);
    cudaGetSymbolAddress((void**)&pagg, g_agg);
    cudaGetSymbolAddress((void**)&pha,  g_ha);
    cudaGetSymbolAddress((void**)&po0,  g_out0);
    cudaGetSymbolAddress((void**)&po1,  g_out1);

    const int smem_edge = Hh * Rr * DHh * DHh * (int)sizeof(float);  // 96 KB
    cudaFuncSetAttribute(edge_score, cudaFuncAttributeMaxDynamicSharedMemorySize, smem_edge);
    cudaFuncSetAttribute(edge_agg,   cudaFuncAttributeMaxDynamicSharedMemorySize, smem_edge);

    const int GEMM_GRID = (Nn + 63) / 64;      // 782
    const int EDGE_GRID = 296;                 // ~2 blocks/SM at 96KB smem
    const int ROW_GRID  = (Nn + 7) / 8;        // 6250 (warp per row, 8 warps/block)

    for (int l = 0; l < Ll; ++l) {
        const float* X = (l == 0) ? h : po0;
        float* OutL = (l == 0) ? po0 : po1;

        cudaMemsetAsync(pden, 0, Nn * Hh * sizeof(float), 0);
        cudaMemsetAsync(pagg, 0, Nn * Dd * sizeof(float), 0);

        typed_gemm<<<GEMM_GRID, 256>>>(X, Wk + l * Tt * Dd * Dd, ntype, pk);
        typed_gemm<<<GEMM_GRID, 256>>>(X, Wq + l * Tt * Dd * Dd, ntype, pq);
        typed_gemm<<<GEMM_GRID, 256>>>(X, Wv + l * Tt * Dd * Dd, ntype, pv);

        edge_score<<<EDGE_GRID, 256, smem_edge>>>(pk, pq, src, dst, etype,
                                                  Watt + l * Hh * Rr * DHh * DHh,
                                                  pri + l * Hh * Rr, pex, pden);
        edge_agg<<<EDGE_GRID, 256, smem_edge>>>(pv, src, dst, etype,
                                                Wmsg + l * Hh * Rr * DHh * DHh,
                                                pex, pden, pagg);

        typed_gemm<<<GEMM_GRID, 256>>>(pagg, Wa + l * Tt * Dd * Dd, ntype, pha);

        node_epilogue<<<ROW_GRID, 256>>>(X, pha, ntype, skip + l * Tt,
                                         lng + l * Dd, lnb + l * Dd, OutL);
    }

    final_mix<<<ROW_GRID, 256>>>(po0, po1, aggw, aggg, aggb, out);
}

// round 2
// speedup vs baseline: 1.5957x; 1.5957x over previous
#include <cuda_runtime.h>
#include <math.h>

#define Nn 50000
#define Ee 400000
#define Dd 128
#define Hh 4
#define DHh 32
#define Tt 3
#define Rr 6
#define Ll 2

// ---------------- scratch (static device globals; no runtime alloc) ----------------
__device__ float g_k[Nn * Dd];
__device__ float g_q[Nn * Dd];
__device__ float g_v[Nn * Dd];
__device__ float g_kp[Rr * Nn * Dd];   // k' = k @ W_att[h,r], layout [R][N][128]
__device__ float g_vp[Rr * Nn * Dd];   // v' = v @ W_msg[h,r]
__device__ float g_ex[Ee * Hh];
__device__ float g_agg[Nn * Dd];
__device__ float g_ha[Nn * Dd];
__device__ float g_out0[Nn * Dd];
__device__ float g_out1[Nn * Dd];
// CSR by dst
__device__ int g_cnt[Nn];
__device__ int g_off[Nn + 1];
__device__ int g_cur[Nn];
__device__ int g_eidx[Ee];

// ---------------- typed per-node GEMM: Out[n,:] = X[n,:] @ W[ntype[n]] ----------------
__global__ void typed_gemm(const float* __restrict__ X, const float* __restrict__ W,
                           const int* __restrict__ ntype, float* __restrict__ Out) {
    __shared__ float Xs[64 * 128];
    __shared__ int ts[64];
    const int r0 = blockIdx.x * 64;
    const int tid = threadIdx.x;

    for (int i = tid; i < 2048; i += 256) {
        int row = r0 + (i >> 5);
        float4 val = make_float4(0.f, 0.f, 0.f, 0.f);
        if (row < Nn) val = ((const float4*)X)[row * 32 + (i & 31)];
        ((float4*)Xs)[i] = val;
    }
    for (int i = tid; i < 64; i += 256) {
        int row = r0 + i;
        ts[i] = (row < Nn) ? ntype[row] : ntype[Nn - 1];
    }
    __syncthreads();

    const int nrows = (Nn - r0 < 64) ? (Nn - r0) : 64;
    const int t0 = ts[0], t1 = ts[nrows - 1];
    const int tx = tid & 31;
    const int ty = tid >> 5;

    for (int t = t0; t <= t1; ++t) {
        const float* Wt = W + t * 16384;
        float acc[8][4];
#pragma unroll
        for (int j = 0; j < 8; ++j) {
            acc[j][0] = 0.f; acc[j][1] = 0.f; acc[j][2] = 0.f; acc[j][3] = 0.f;
        }
#pragma unroll 4
        for (int k = 0; k < 128; ++k) {
            float4 w4 = ((const float4*)(Wt + k * 128))[tx];
#pragma unroll
            for (int j = 0; j < 8; ++j) {
                float xv = Xs[(ty * 8 + j) * 128 + k];
                acc[j][0] += xv * w4.x;
                acc[j][1] += xv * w4.y;
                acc[j][2] += xv * w4.z;
                acc[j][3] += xv * w4.w;
            }
        }
#pragma unroll
        for (int j = 0; j < 8; ++j) {
            int lr = ty * 8 + j;
            int row = r0 + lr;
            if (row < Nn && ts[lr] == t) {
                float4 o;
                o.x = acc[j][0]; o.y = acc[j][1]; o.z = acc[j][2]; o.w = acc[j][3];
                ((float4*)Out)[row * 32 + tx] = o;
            }
        }
    }
}

// ---------------- expand: Out[r][n][h*32+o] = sum_d In[n][h*32+d] * W[h][r][d][o] ----------------
// Per-head 32x32 GEMMs for all R relations; W stays in L1 (16KB per r, shared by all blocks).
__global__ void expand(const float* __restrict__ In, const float* __restrict__ W,
                       float* __restrict__ Out) {
    __shared__ float Xs[64 * 128];
    const int r0 = blockIdx.x * 64;
    const int tid = threadIdx.x;

    for (int i = tid; i < 2048; i += 256) {
        int row = r0 + (i >> 5);
        float4 val = make_float4(0.f, 0.f, 0.f, 0.f);
        if (row < Nn) val = ((const float4*)In)[row * 32 + (i & 31)];
        ((float4*)Xs)[i] = val;
    }
    __syncthreads();

    const int tx = tid & 31;
    const int ty = tid >> 5;
    const int h = tx >> 3;

    for (int r = 0; r < Rr; ++r) {
        float acc[8][4];
#pragma unroll
        for (int j = 0; j < 8; ++j) {
            acc[j][0] = 0.f; acc[j][1] = 0.f; acc[j][2] = 0.f; acc[j][3] = 0.f;
        }
#pragma unroll 4
        for (int d = 0; d < 32; ++d) {
            float4 w4 = *(const float4*)(W + (((h * Rr + r) * 32 + d) * 32) + (tx & 7) * 4);
#pragma unroll
            for (int j = 0; j < 8; ++j) {
                float xv = Xs[(ty * 8 + j) * 128 + h * 32 + d];
                acc[j][0] += xv * w4.x;
                acc[j][1] += xv * w4.y;
                acc[j][2] += xv * w4.z;
                acc[j][3] += xv * w4.w;
            }
        }
#pragma unroll
        for (int j = 0; j < 8; ++j) {
            int row = r0 + ty * 8 + j;
            if (row < Nn) {
                float4 o;
                o.x = acc[j][0]; o.y = acc[j][1]; o.z = acc[j][2]; o.w = acc[j][3];
                ((float4*)Out)[(r * Nn + row) * 32 + tx] = o;
            }
        }
    }
}

// ---------------- CSR build ----------------
__global__ void hist_dst(const int* __restrict__ dst, int* __restrict__ cnt) {
    for (int e = blockIdx.x * blockDim.x + threadIdx.x; e < Ee; e += gridDim.x * blockDim.x)
        atomicAdd(&cnt[dst[e]], 1);
}

__global__ void scan_offsets(const int* __restrict__ cnt, int* __restrict__ off) {
    __shared__ int wsum[32];
    __shared__ int carry;
    const int lane = threadIdx.x & 31;
    const int w = threadIdx.x >> 5;
    if (threadIdx.x == 0) { carry = 0; off[0] = 0; }
    __syncthreads();
    for (int base = 0; base < Nn; base += 1024) {
        int i = base + threadIdx.x;
        int x = (i < Nn) ? cnt[i] : 0;
#pragma unroll
        for (int o = 1; o < 32; o <<= 1) {
            int t = __shfl_up_sync(0xffffffffu, x, o);
            if (lane >= o) x += t;
        }
        if (lane == 31) wsum[w] = x;
        __syncthreads();
        if (w == 0) {
            int s = wsum[lane];
#pragma unroll
            for (int o = 1; o < 32; o <<= 1) {
                int t = __shfl_up_sync(0xffffffffu, s, o);
                if (lane >= o) s += t;
            }
            wsum[lane] = s;
        }
        __syncthreads();
        int incl = x + (w > 0 ? wsum[w - 1] : 0) + carry;
        if (i < Nn) off[i + 1] = incl;
        __syncthreads();
        if (threadIdx.x == 1023) carry = incl;
        __syncthreads();
    }
}

__global__ void scatter_edges(const int* __restrict__ dst, int* __restrict__ cur,
                              int* __restrict__ eidx) {
    for (int e = blockIdx.x * blockDim.x + threadIdx.x; e < Ee; e += gridDim.x * blockDim.x) {
        int p = atomicAdd(&cur[dst[e]], 1);
        eidx[p] = e;
    }
}

// ---------------- fused edge pass: warp per dst node, no atomics ----------------
// loop1: ex[e,h]=exp(dot(k'[src,r],q[dst])*pri/sqrt(DH)); den in regs
// loop2: agg[dst] = sum att * v'[src,r]
__global__ void edge_fused(const float* __restrict__ kp, const float* __restrict__ vp,
                           const float* __restrict__ qq,
                           const int* __restrict__ src, const int* __restrict__ etype,
                           const int* __restrict__ off, const int* __restrict__ eidx,
                           const float* __restrict__ pri,
                           float* __restrict__ ex, float* __restrict__ agg) {
    __shared__ float Pri[Hh * Rr];
    if (threadIdx.x < Hh * Rr) Pri[threadIdx.x] = pri[threadIdx.x];
    __syncthreads();

    const int lane = threadIdx.x & 31;
    const int n = blockIdx.x * (blockDim.x >> 5) + (threadIdx.x >> 5);
    if (n >= Nn) return;
    const int h = lane >> 3;
    const int beg = off[n], end = off[n + 1];

    float4 q4 = ((const float4*)(qq + n * Dd))[lane];
    float den = 0.f;
    for (int i = beg; i < end; ++i) {
        int e = eidx[i];
        int s = src[e], r = etype[e];
        float4 k4 = ((const float4*)kp)[(r * Nn + s) * 32 + lane];
        float p = k4.x * q4.x + k4.y * q4.y + k4.z * q4.z + k4.w * q4.w;
        p += __shfl_xor_sync(0xffffffffu, p, 1);
        p += __shfl_xor_sync(0xffffffffu, p, 2);
        p += __shfl_xor_sync(0xffffffffu, p, 4);
        float ev = expf(p * Pri[h * Rr + r] * 0.17677669529663687f);
        den += ev;
        if ((lane & 7) == 0) ex[e * Hh + h] = ev;
    }
    __threadfence_block();
    __syncwarp();
    float invd = (den > 0.f) ? (1.f / den) : 0.f;

    float4 acc = make_float4(0.f, 0.f, 0.f, 0.f);
    for (int i = beg; i < end; ++i) {
        int e = eidx[i];
        int s = src[e], r = etype[e];
        float att = ex[e * Hh + h] * invd;
        float4 v4 = ((const float4*)vp)[(r * Nn + s) * 32 + lane];
        acc.x += att * v4.x;
        acc.y += att * v4.y;
        acc.z += att * v4.z;
        acc.w += att * v4.w;
    }
    ((float4*)agg)[n * 32 + lane] = acc;
}

// ---------------- per-node: pre = x*(2-sk) + h_a*sk ; out = LN(pre) ----------------
__global__ void node_epilogue(const float* __restrict__ X, const float* __restrict__ Ha,
                              const int* __restrict__ ntype,
                              const float* __restrict__ skip,
                              const float* __restrict__ lng, const float* __restrict__ lnb,
                              float* __restrict__ OutL) {
    const int lane = threadIdx.x & 31;
    const int row = blockIdx.x * (blockDim.x >> 5) + (threadIdx.x >> 5);
    if (row >= Nn) return;
    int t = ntype[row];
    float sk = 1.f / (1.f + expf(-skip[t]));

    float4 x4 = ((const float4*)X)[row * 32 + lane];
    float4 h4 = ((const float4*)Ha)[row * 32 + lane];
    float p0 = x4.x * (2.f - sk) + h4.x * sk;
    float p1 = x4.y * (2.f - sk) + h4.y * sk;
    float p2 = x4.z * (2.f - sk) + h4.z * sk;
    float p3 = x4.w * (2.f - sk) + h4.w * sk;

    float s = p0 + p1 + p2 + p3;
#pragma unroll
    for (int off = 16; off > 0; off >>= 1) s += __shfl_xor_sync(0xffffffffu, s, off);
    float mu = s * (1.f / 128.f);
    float d0 = p0 - mu, d1 = p1 - mu, d2 = p2 - mu, d3 = p3 - mu;
    float qv = d0 * d0 + d1 * d1 + d2 * d2 + d3 * d3;
#pragma unroll
    for (int off = 16; off > 0; off >>= 1) qv += __shfl_xor_sync(0xffffffffu, qv, off);
    float inv = rsqrtf(qv * (1.f / 128.f) + 1e-5f);

    float4 g4 = ((const float4*)lng)[lane];
    float4 b4 = ((const float4*)lnb)[lane];
    float4 o;
    o.x = d0 * inv * g4.x + b4.x;
    o.y = d1 * inv * g4.y + b4.y;
    o.z = d2 * inv * g4.z + b4.z;
    o.w = d3 * inv * g4.w + b4.w;
    ((float4*)OutL)[row * 32 + lane] = o;
}

// ---------------- final: mixed = softmax(agg_w) . outs ; out = LN(mixed) ----------------
__global__ void final_mix(const float* __restrict__ o0, const float* __restrict__ o1,
                          const float* __restrict__ aw,
                          const float* __restrict__ gg, const float* __restrict__ bb,
                          float* __restrict__ out) {
    const int lane = threadIdx.x & 31;
    const int row = blockIdx.x * (blockDim.x >> 5) + (threadIdx.x >> 5);
    if (row >= Nn) return;
    float e0 = expf(aw[0]), e1 = expf(aw[1]);
    float w0 = e0 / (e0 + e1), w1 = e1 / (e0 + e1);

    float4 a4 = ((const float4*)o0)[row * 32 + lane];
    float4 c4 = ((const float4*)o1)[row * 32 + lane];
    float p0 = w0 * a4.x + w1 * c4.x;
    float p1 = w0 * a4.y + w1 * c4.y;
    float p2 = w0 * a4.z + w1 * c4.z;
    float p3 = w0 * a4.w + w1 * c4.w;

    float s = p0 + p1 + p2 + p3;
#pragma unroll
    for (int off = 16; off > 0; off >>= 1) s += __shfl_xor_sync(0xffffffffu, s, off);
    float mu = s * (1.f / 128.f);
    float d0 = p0 - mu, d1 = p1 - mu, d2 = p2 - mu, d3 = p3 - mu;
    float qv = d0 * d0 + d1 * d1 + d2 * d2 + d3 * d3;
#pragma unroll
    for (int off = 16; off > 0; off >>= 1) qv += __shfl_xor_sync(0xffffffffu, qv, off);
    float inv = rsqrtf(qv * (1.f / 128.f) + 1e-5f);

    float4 g4 = ((const float4*)gg)[lane];
    float4 b4 = ((const float4*)bb)[lane];
    float4 o;
    o.x = d0 * inv * g4.x + b4.x;
    o.y = d1 * inv * g4.y + b4.y;
    o.z = d2 * inv * g4.z + b4.z;
    o.w = d3 * inv * g4.w + b4.w;
    ((float4*)out)[row * 32 + lane] = o;
}

extern "C" void kernel_launch(void* const* d_in, const int* in_sizes, int n_in,
                              void* d_out, int out_size) {
    (void)in_sizes; (void)n_in; (void)out_size;
    const float* h     = (const float*)d_in[0];
    const int*   src   = (const int*)d_in[1];
    const int*   dst   = (const int*)d_in[2];
    const int*   ntype = (const int*)d_in[3];
    const int*   etype = (const int*)d_in[4];
    const float* Wk    = (const float*)d_in[5];
    const float* Wq    = (const float*)d_in[6];
    const float* Wv    = (const float*)d_in[7];
    const float* Wa    = (const float*)d_in[8];
    const float* Watt  = (const float*)d_in[9];
    const float* Wmsg  = (const float*)d_in[10];
    const float* pri   = (const float*)d_in[11];
    const float* skip  = (const float*)d_in[12];
    const float* lng   = (const float*)d_in[13];
    const float* lnb   = (const float*)d_in[14];
    const float* aggw  = (const float*)d_in[15];
    const float* aggg  = (const float*)d_in[16];
    const float* aggb  = (const float*)d_in[17];
    float* out = (float*)d_out;

    float *pk, *pq, *pv, *pkp, *pvp, *pex, *pagg, *pha, *po0, *po1;
    int *pcnt, *poff, *pcur, *peidx;
    cudaGetSymbolAddress((void**)&pk,   g_k);
    cudaGetSymbolAddress((void**)&pq,   g_q);
    cudaGetSymbolAddress((void**)&pv,   g_v);
    cudaGetSymbolAddress((void**)&pkp,  g_kp);
    cudaGetSymbolAddress((void**)&pvp,  g_vp);
    cudaGetSymbolAddress((void**)&pex,  g_ex);
    cudaGetSymbolAddress((void**)&pagg, g_agg);
    cudaGetSymbolAddress((void**)&pha,  g_ha);
    cudaGetSymbolAddress((void**)&po0,  g_out0);
    cudaGetSymbolAddress((void**)&po1,  g_out1);
    cudaGetSymbolAddress((void**)&pcnt, g_cnt);
    cudaGetSymbolAddress((void**)&poff, g_off);
    cudaGetSymbolAddress((void**)&pcur, g_cur);
    cudaGetSymbolAddress((void**)&peidx, g_eidx);

    const int GEMM_GRID = (Nn + 63) / 64;   // 782
    const int ROW_GRID  = (Nn + 7) / 8;     // 6250
    const int EGRID     = 592;

    // ---- CSR by dst (graph is static across layers) ----
    cudaMemsetAsync(pcnt, 0, Nn * sizeof(int), 0);
    hist_dst<<<EGRID, 256>>>(dst, pcnt);
    scan_offsets<<<1, 1024>>>(pcnt, poff);
    cudaMemcpyAsync(pcur, poff, Nn * sizeof(int), cudaMemcpyDeviceToDevice, 0);
    scatter_edges<<<EGRID, 256>>>(dst, pcur, peidx);

    for (int l = 0; l < Ll; ++l) {
        const float* X = (l == 0) ? h : po0;
        float* OutL = (l == 0) ? po0 : po1;
        const float* WattL = Watt + l * Hh * Rr * DHh * DHh;
        const float* WmsgL = Wmsg + l * Hh * Rr * DHh * DHh;

        typed_gemm<<<GEMM_GRID, 256>>>(X, Wk + l * Tt * Dd * Dd, ntype, pk);
        typed_gemm<<<GEMM_GRID, 256>>>(X, Wq + l * Tt * Dd * Dd, ntype, pq);
        typed_gemm<<<GEMM_GRID, 256>>>(X, Wv + l * Tt * Dd * Dd, ntype, pv);

        expand<<<GEMM_GRID, 256>>>(pk, WattL, pkp);
        expand<<<GEMM_GRID, 256>>>(pv, WmsgL, pvp);

        edge_fused<<<ROW_GRID, 256>>>(pkp, pvp, pq, src, etype, poff, peidx,
                                      pri + l * Hh * Rr, pex, pagg);

        typed_gemm<<<GEMM_GRID, 256>>>(pagg, Wa + l * Tt * Dd * Dd, ntype, pha);

        node_epilogue<<<ROW_GRID, 256>>>(X, pha, ntype, skip + l * Tt,
                                         lng + l * Dd, lnb + l * Dd, OutL);
    }

    final_mix<<<ROW_GRID, 256>>>(po0, po1, aggw, aggg, aggb, out);
}

// round 3
// speedup vs baseline: 3.2182x; 2.0168x over previous
#include <cuda_runtime.h>
#include <math.h>

#define Nn 50000
#define Ee 400000
#define Dd 128
#define Hh 4
#define DHh 32
#define Tt 3
#define Rr 6
#define Ll 2

// ---------------- scratch ----------------
__device__ float g_k[Nn * Dd];
__device__ float g_q[Nn * Dd];
__device__ float g_v[Nn * Dd];
__device__ float g_kp[Rr * Nn * Dd];
__device__ float g_vp[Rr * Nn * Dd];
__device__ float g_ex[Ee * Hh];
__device__ float g_agg[Nn * Dd];
__device__ float g_ha[Nn * Dd];
__device__ float g_out0[Nn * Dd];
__device__ float g_out1[Nn * Dd];
__device__ int g_cnt[Nn];
__device__ int g_off[Nn + 1];
__device__ int g_cur[Nn];
__device__ int g_eidx[Ee];

// ---------------- tf32 helpers ----------------
__device__ __forceinline__ unsigned f2tf(float f) {
    unsigned u;
    asm("cvt.rna.tf32.f32 %0, %1;" : "=r"(u) : "f"(f));
    return u;
}

__device__ __forceinline__ void mma8(float c[4], const unsigned a[4],
                                     unsigned b0, unsigned b1) {
    asm volatile(
        "mma.sync.aligned.m16n8k8.row.col.f32.tf32.tf32.f32 "
        "{%0,%1,%2,%3},{%4,%5,%6,%7},{%8,%9},{%0,%1,%2,%3};"
        : "+f"(c[0]), "+f"(c[1]), "+f"(c[2]), "+f"(c[3])
        : "r"(a[0]), "r"(a[1]), "r"(a[2]), "r"(a[3]), "r"(b0), "r"(b1));
}

// ---------------- typed GEMM, tf32 tensor cores ----------------
// block = 128 rows x 128 cols, K=128 in 4 chunks of 32. 8 warps: 4(m) x 2(n),
// warp tile 32x64. ntype sorted -> <=2 types per block; loop t with predicated store.
__global__ void typed_gemm_tc(const float* __restrict__ X, const float* __restrict__ W,
                              const int* __restrict__ ntype, float* __restrict__ Out) {
    __shared__ unsigned Xs[128][36];   // padded: bank = 4*gid + tig
    __shared__ unsigned Ws[32][132];
    __shared__ int ts[128];
    const int r0 = blockIdx.x * 128;
    const int tid = threadIdx.x;

    for (int i = tid; i < 128; i += 256) {
        int row = r0 + i;
        ts[i] = (row < Nn) ? ntype[row] : ntype[Nn - 1];
    }
    __syncthreads();
    const int nrows = (Nn - r0 < 128) ? (Nn - r0) : 128;
    const int t0 = ts[0], t1 = ts[nrows - 1];

    const int wid = tid >> 5, lane = tid & 31;
    const int gid = lane >> 2, tig = lane & 3;
    const int wm = wid & 3, wn = wid >> 2;

    for (int t = t0; t <= t1; ++t) {
        const float* Wt = W + t * 16384;
        float c[2][8][4];
#pragma unroll
        for (int mi = 0; mi < 2; ++mi)
#pragma unroll
            for (int ni = 0; ni < 8; ++ni) {
                c[mi][ni][0] = 0.f; c[mi][ni][1] = 0.f;
                c[mi][ni][2] = 0.f; c[mi][ni][3] = 0.f;
            }

        for (int kc = 0; kc < 4; ++kc) {
            // X chunk: 128 rows x 32 cols
#pragma unroll
            for (int j = 0; j < 4; ++j) {
                int idx = tid + j * 256;
                int row = idx >> 3, q = idx & 7;
                float4 v = make_float4(0.f, 0.f, 0.f, 0.f);
                if (r0 + row < Nn)
                    v = *(const float4*)(X + (r0 + row) * 128 + kc * 32 + q * 4);
                unsigned* d = &Xs[row][q * 4];
                d[0] = f2tf(v.x); d[1] = f2tf(v.y); d[2] = f2tf(v.z); d[3] = f2tf(v.w);
            }
            // W chunk: 32 rows(k) x 128 cols
#pragma unroll
            for (int j = 0; j < 4; ++j) {
                int idx = tid + j * 256;
                int kr = idx >> 5, q = idx & 31;
                float4 v = *(const float4*)(Wt + (kc * 32 + kr) * 128 + q * 4);
                unsigned* d = &Ws[kr][q * 4];
                d[0] = f2tf(v.x); d[1] = f2tf(v.y); d[2] = f2tf(v.z); d[3] = f2tf(v.w);
            }
            __syncthreads();
#pragma unroll
            for (int ks = 0; ks < 4; ++ks) {
                int kb = ks * 8;
                unsigned a[2][4];
#pragma unroll
                for (int mi = 0; mi < 2; ++mi) {
                    int rl = wm * 32 + mi * 16 + gid;
                    a[mi][0] = Xs[rl][kb + tig];
                    a[mi][1] = Xs[rl + 8][kb + tig];
                    a[mi][2] = Xs[rl][kb + tig + 4];
                    a[mi][3] = Xs[rl + 8][kb + tig + 4];
                }
#pragma unroll
                for (int ni = 0; ni < 8; ++ni) {
                    int cc = wn * 64 + ni * 8 + gid;
                    unsigned b0 = Ws[kb + tig][cc];
                    unsigned b1 = Ws[kb + tig + 4][cc];
                    mma8(c[0][ni], a[0], b0, b1);
                    mma8(c[1][ni], a[1], b0, b1);
                }
            }
            __syncthreads();
        }
        // store (predicated on row type)
#pragma unroll
        for (int mi = 0; mi < 2; ++mi) {
            int rl = wm * 32 + mi * 16 + gid;
            int rh = rl + 8;
#pragma unroll
            for (int ni = 0; ni < 8; ++ni) {
                int cc = wn * 64 + ni * 8 + 2 * tig;
                if (r0 + rl < Nn && ts[rl] == t)
                    *(float2*)(Out + (r0 + rl) * 128 + cc) =
                        make_float2(c[mi][ni][0], c[mi][ni][1]);
                if (r0 + rh < Nn && ts[rh] == t)
                    *(float2*)(Out + (r0 + rh) * 128 + cc) =
                        make_float2(c[mi][ni][2], c[mi][ni][3]);
            }
        }
    }
}

// ---------------- expand, tf32 tensor cores ----------------
// Out[r][n][h*32+o] = sum_d In[n][h*32+d] * W[h][r][d][o]
// block = 64 rows; 8 warps: 2(m) x 4(head). K=32 per head. Loops r=0..5.
__global__ void expand_tc(const float* __restrict__ In, const float* __restrict__ W,
                          float* __restrict__ Out) {
    extern __shared__ unsigned sm[];
    unsigned* Xs = sm;                 // [64][132]
    unsigned* Wsm = sm + 64 * 132;     // [4][32][36]
    const int r0 = blockIdx.x * 64;
    const int tid = threadIdx.x;
    const int wid = tid >> 5, lane = tid & 31;
    const int gid = lane >> 2, tig = lane & 3;
    const int wm = wid & 1, h = wid >> 1;

    // X tile: 64 rows x 128
#pragma unroll
    for (int j = 0; j < 8; ++j) {
        int idx = tid + j * 256;
        int row = idx >> 5, q = idx & 31;
        float4 v = make_float4(0.f, 0.f, 0.f, 0.f);
        if (r0 + row < Nn)
            v = *(const float4*)(In + (r0 + row) * 128 + q * 4);
        unsigned* d = &Xs[row * 132 + q * 4];
        d[0] = f2tf(v.x); d[1] = f2tf(v.y); d[2] = f2tf(v.z); d[3] = f2tf(v.w);
    }

    for (int r = 0; r < Rr; ++r) {
        __syncthreads();   // protect Wsm from previous iteration's readers
        // W(r): 4 heads x 32 x 32
#pragma unroll
        for (int j = 0; j < 4; ++j) {
            int idx = tid + j * 256;
            int hh = idx >> 8, rem = idx & 255;
            int dd = rem >> 3, q = rem & 7;
            float4 v = *(const float4*)(W + (((hh * Rr + r) * 32 + dd) * 32) + q * 4);
            unsigned* d = &Wsm[(hh * 32 + dd) * 36 + q * 4];
            d[0] = f2tf(v.x); d[1] = f2tf(v.y); d[2] = f2tf(v.z); d[3] = f2tf(v.w);
        }
        __syncthreads();

        float c[2][4][4];
#pragma unroll
        for (int mi = 0; mi < 2; ++mi)
#pragma unroll
            for (int ni = 0; ni < 4; ++ni) {
                c[mi][ni][0] = 0.f; c[mi][ni][1] = 0.f;
                c[mi][ni][2] = 0.f; c[mi][ni][3] = 0.f;
            }
#pragma unroll
        for (int ks = 0; ks < 4; ++ks) {
            int kb = ks * 8;
            unsigned a[2][4];
#pragma unroll
            for (int mi = 0; mi < 2; ++mi) {
                int rl = wm * 32 + mi * 16 + gid;
                int col = h * 32 + kb + tig;
                a[mi][0] = Xs[rl * 132 + col];
                a[mi][1] = Xs[(rl + 8) * 132 + col];
                a[mi][2] = Xs[rl * 132 + col + 4];
                a[mi][3] = Xs[(rl + 8) * 132 + col + 4];
            }
#pragma unroll
            for (int ni = 0; ni < 4; ++ni) {
                int cc = ni * 8 + gid;
                unsigned b0 = Wsm[(h * 32 + kb + tig) * 36 + cc];
                unsigned b1 = Wsm[(h * 32 + kb + tig + 4) * 36 + cc];
                mma8(c[0][ni], a[0], b0, b1);
                mma8(c[1][ni], a[1], b0, b1);
            }
        }
#pragma unroll
        for (int mi = 0; mi < 2; ++mi) {
            int rl = wm * 32 + mi * 16 + gid;
            int rh = rl + 8;
#pragma unroll
            for (int ni = 0; ni < 4; ++ni) {
                int cc = h * 32 + ni * 8 + 2 * tig;
                if (r0 + rl < Nn)
                    *(float2*)(Out + ((long)r * Nn + r0 + rl) * 128 + cc) =
                        make_float2(c[mi][ni][0], c[mi][ni][1]);
                if (r0 + rh < Nn)
                    *(float2*)(Out + ((long)r * Nn + r0 + rh) * 128 + cc) =
                        make_float2(c[mi][ni][2], c[mi][ni][3]);
            }
        }
    }
}

// ---------------- CSR build ----------------
__global__ void hist_dst(const int* __restrict__ dst, int* __restrict__ cnt) {
    for (int e = blockIdx.x * blockDim.x + threadIdx.x; e < Ee; e += gridDim.x * blockDim.x)
        atomicAdd(&cnt[dst[e]], 1);
}

__global__ void scan_offsets(const int* __restrict__ cnt, int* __restrict__ off) {
    __shared__ int wsum[32];
    __shared__ int carry;
    const int lane = threadIdx.x & 31;
    const int w = threadIdx.x >> 5;
    if (threadIdx.x == 0) { carry = 0; off[0] = 0; }
    __syncthreads();
    for (int base = 0; base < Nn; base += 1024) {
        int i = base + threadIdx.x;
        int x = (i < Nn) ? cnt[i] : 0;
#pragma unroll
        for (int o = 1; o < 32; o <<= 1) {
            int t = __shfl_up_sync(0xffffffffu, x, o);
            if (lane >= o) x += t;
        }
        if (lane == 31) wsum[w] = x;
        __syncthreads();
        if (w == 0) {
            int s = wsum[lane];
#pragma unroll
            for (int o = 1; o < 32; o <<= 1) {
                int t = __shfl_up_sync(0xffffffffu, s, o);
                if (lane >= o) s += t;
            }
            wsum[lane] = s;
        }
        __syncthreads();
        int incl = x + (w > 0 ? wsum[w - 1] : 0) + carry;
        if (i < Nn) off[i + 1] = incl;
        __syncthreads();
        if (threadIdx.x == 1023) carry = incl;
        __syncthreads();
    }
}

__global__ void scatter_edges(const int* __restrict__ dst, int* __restrict__ cur,
                              int* __restrict__ eidx) {
    for (int e = blockIdx.x * blockDim.x + threadIdx.x; e < Ee; e += gridDim.x * blockDim.x) {
        int p = atomicAdd(&cur[dst[e]], 1);
        eidx[p] = e;
    }
}

// ---------------- fused edge pass: warp per dst node, no atomics ----------------
__global__ void edge_fused(const float* __restrict__ kp, const float* __restrict__ vp,
                           const float* __restrict__ qq,
                           const int* __restrict__ src, const int* __restrict__ etype,
                           const int* __restrict__ off, const int* __restrict__ eidx,
                           const float* __restrict__ pri,
                           float* __restrict__ ex, float* __restrict__ agg) {
    __shared__ float Pri[Hh * Rr];
    if (threadIdx.x < Hh * Rr) Pri[threadIdx.x] = pri[threadIdx.x];
    __syncthreads();

    const int lane = threadIdx.x & 31;
    const int n = blockIdx.x * (blockDim.x >> 5) + (threadIdx.x >> 5);
    if (n >= Nn) return;
    const int h = lane >> 3;
    const int beg = off[n], end = off[n + 1];

    float4 q4 = ((const float4*)(qq + n * Dd))[lane];
    float den = 0.f;
    for (int i = beg; i < end; ++i) {
        int e = eidx[i];
        int s = src[e], r = etype[e];
        float4 k4 = ((const float4*)kp)[((long)r * Nn + s) * 32 + lane];
        float p = k4.x * q4.x + k4.y * q4.y + k4.z * q4.z + k4.w * q4.w;
        p += __shfl_xor_sync(0xffffffffu, p, 1);
        p += __shfl_xor_sync(0xffffffffu, p, 2);
        p += __shfl_xor_sync(0xffffffffu, p, 4);
        float ev = expf(p * Pri[h * Rr + r] * 0.17677669529663687f);
        den += ev;
        if ((lane & 7) == 0) ex[e * Hh + h] = ev;
    }
    __threadfence_block();
    __syncwarp();
    float invd = (den > 0.f) ? (1.f / den) : 0.f;

    float4 acc = make_float4(0.f, 0.f, 0.f, 0.f);
    for (int i = beg; i < end; ++i) {
        int e = eidx[i];
        int s = src[e], r = etype[e];
        float att = ex[e * Hh + h] * invd;
        float4 v4 = ((const float4*)vp)[((long)r * Nn + s) * 32 + lane];
        acc.x += att * v4.x;
        acc.y += att * v4.y;
        acc.z += att * v4.z;
        acc.w += att * v4.w;
    }
    ((float4*)agg)[n * 32 + lane] = acc;
}

// ---------------- per-node epilogue ----------------
__global__ void node_epilogue(const float* __restrict__ X, const float* __restrict__ Ha,
                              const int* __restrict__ ntype,
                              const float* __restrict__ skip,
                              const float* __restrict__ lng, const float* __restrict__ lnb,
                              float* __restrict__ OutL) {
    const int lane = threadIdx.x & 31;
    const int row = blockIdx.x * (blockDim.x >> 5) + (threadIdx.x >> 5);
    if (row >= Nn) return;
    int t = ntype[row];
    float sk = 1.f / (1.f + expf(-skip[t]));

    float4 x4 = ((const float4*)X)[row * 32 + lane];
    float4 h4 = ((const float4*)Ha)[row * 32 + lane];
    float p0 = x4.x * (2.f - sk) + h4.x * sk;
    float p1 = x4.y * (2.f - sk) + h4.y * sk;
    float p2 = x4.z * (2.f - sk) + h4.z * sk;
    float p3 = x4.w * (2.f - sk) + h4.w * sk;

    float s = p0 + p1 + p2 + p3;
#pragma unroll
    for (int off = 16; off > 0; off >>= 1) s += __shfl_xor_sync(0xffffffffu, s, off);
    float mu = s * (1.f / 128.f);
    float d0 = p0 - mu, d1 = p1 - mu, d2 = p2 - mu, d3 = p3 - mu;
    float qv = d0 * d0 + d1 * d1 + d2 * d2 + d3 * d3;
#pragma unroll
    for (int off = 16; off > 0; off >>= 1) qv += __shfl_xor_sync(0xffffffffu, qv, off);
    float inv = rsqrtf(qv * (1.f / 128.f) + 1e-5f);

    float4 g4 = ((const float4*)lng)[lane];
    float4 b4 = ((const float4*)lnb)[lane];
    float4 o;
    o.x = d0 * inv * g4.x + b4.x;
    o.y = d1 * inv * g4.y + b4.y;
    o.z = d2 * inv * g4.z + b4.z;
    o.w = d3 * inv * g4.w + b4.w;
    ((float4*)OutL)[row * 32 + lane] = o;
}

// ---------------- final mix + LN ----------------
__global__ void final_mix(const float* __restrict__ o0, const float* __restrict__ o1,
                          const float* __restrict__ aw,
                          const float* __restrict__ gg, const float* __restrict__ bb,
                          float* __restrict__ out) {
    const int lane = threadIdx.x & 31;
    const int row = blockIdx.x * (blockDim.x >> 5) + (threadIdx.x >> 5);
    if (row >= Nn) return;
    float e0 = expf(aw[0]), e1 = expf(aw[1]);
    float w0 = e0 / (e0 + e1), w1 = e1 / (e0 + e1);

    float4 a4 = ((const float4*)o0)[row * 32 + lane];
    float4 c4 = ((const float4*)o1)[row * 32 + lane];
    float p0 = w0 * a4.x + w1 * c4.x;
    float p1 = w0 * a4.y + w1 * c4.y;
    float p2 = w0 * a4.z + w1 * c4.z;
    float p3 = w0 * a4.w + w1 * c4.w;

    float s = p0 + p1 + p2 + p3;
#pragma unroll
    for (int off = 16; off > 0; off >>= 1) s += __shfl_xor_sync(0xffffffffu, s, off);
    float mu = s * (1.f / 128.f);
    float d0 = p0 - mu, d1 = p1 - mu, d2 = p2 - mu, d3 = p3 - mu;
    float qv = d0 * d0 + d1 * d1 + d2 * d2 + d3 * d3;
#pragma unroll
    for (int off = 16; off > 0; off >>= 1) qv += __shfl_xor_sync(0xffffffffu, qv, off);
    float inv = rsqrtf(qv * (1.f / 128.f) + 1e-5f);

    float4 g4 = ((const float4*)gg)[lane];
    float4 b4 = ((const float4*)bb)[lane];
    float4 o;
    o.x = d0 * inv * g4.x + b4.x;
    o.y = d1 * inv * g4.y + b4.y;
    o.z = d2 * inv * g4.z + b4.z;
    o.w = d3 * inv * g4.w + b4.w;
    ((float4*)out)[row * 32 + lane] = o;
}

extern "C" void kernel_launch(void* const* d_in, const int* in_sizes, int n_in,
                              void* d_out, int out_size) {
    (void)in_sizes; (void)n_in; (void)out_size;
    const float* h     = (const float*)d_in[0];
    const int*   src   = (const int*)d_in[1];
    const int*   dst   = (const int*)d_in[2];
    const int*   ntype = (const int*)d_in[3];
    const int*   etype = (const int*)d_in[4];
    const float* Wk    = (const float*)d_in[5];
    const float* Wq    = (const float*)d_in[6];
    const float* Wv    = (const float*)d_in[7];
    const float* Wa    = (const float*)d_in[8];
    const float* Watt  = (const float*)d_in[9];
    const float* Wmsg  = (const float*)d_in[10];
    const float* pri   = (const float*)d_in[11];
    const float* skip  = (const float*)d_in[12];
    const float* lng   = (const float*)d_in[13];
    const float* lnb   = (const float*)d_in[14];
    const float* aggw  = (const float*)d_in[15];
    const float* aggg  = (const float*)d_in[16];
    const float* aggb  = (const float*)d_in[17];
    float* out = (float*)d_out;

    float *pk, *pq, *pv, *pkp, *pvp, *pex, *pagg, *pha, *po0, *po1;
    int *pcnt, *poff, *pcur, *peidx;
    cudaGetSymbolAddress((void**)&pk,   g_k);
    cudaGetSymbolAddress((void**)&pq,   g_q);
    cudaGetSymbolAddress((void**)&pv,   g_v);
    cudaGetSymbolAddress((void**)&pkp,  g_kp);
    cudaGetSymbolAddress((void**)&pvp,  g_vp);
    cudaGetSymbolAddress((void**)&pex,  g_ex);
    cudaGetSymbolAddress((void**)&pagg, g_agg);
    cudaGetSymbolAddress((void**)&pha,  g_ha);
    cudaGetSymbolAddress((void**)&po0,  g_out0);
    cudaGetSymbolAddress((void**)&po1,  g_out1);
    cudaGetSymbolAddress((void**)&pcnt, g_cnt);
    cudaGetSymbolAddress((void**)&poff, g_off);
    cudaGetSymbolAddress((void**)&pcur, g_cur);
    cudaGetSymbolAddress((void**)&peidx, g_eidx);

    const int EXP_SMEM = (64 * 132 + 4 * 32 * 36) * (int)sizeof(unsigned);  // 52224
    cudaFuncSetAttribute(expand_tc, cudaFuncAttributeMaxDynamicSharedMemorySize, EXP_SMEM);

    const int TG_GRID  = (Nn + 127) / 128;  // 391
    const int EX_GRID  = (Nn + 63) / 64;    // 782
    const int ROW_GRID = (Nn + 7) / 8;      // 6250
    const int EGRID    = 592;

    // ---- CSR by dst (graph static across layers) ----
    cudaMemsetAsync(pcnt, 0, Nn * sizeof(int), 0);
    hist_dst<<<EGRID, 256>>>(dst, pcnt);
    scan_offsets<<<1, 1024>>>(pcnt, poff);
    cudaMemcpyAsync(pcur, poff, Nn * sizeof(int), cudaMemcpyDeviceToDevice, 0);
    scatter_edges<<<EGRID, 256>>>(dst, pcur, peidx);

    for (int l = 0; l < Ll; ++l) {
        const float* X = (l == 0) ? h : po0;
        float* OutL = (l == 0) ? po0 : po1;
        const float* WattL = Watt + l * Hh * Rr * DHh * DHh;
        const float* WmsgL = Wmsg + l * Hh * Rr * DHh * DHh;

        typed_gemm_tc<<<TG_GRID, 256>>>(X, Wk + l * Tt * Dd * Dd, ntype, pk);
        typed_gemm_tc<<<TG_GRID, 256>>>(X, Wq + l * Tt * Dd * Dd, ntype, pq);
        typed_gemm_tc<<<TG_GRID, 256>>>(X, Wv + l * Tt * Dd * Dd, ntype, pv);

        expand_tc<<<EX_GRID, 256, EXP_SMEM>>>(pk, WattL, pkp);
        expand_tc<<<EX_GRID, 256, EXP_SMEM>>>(pv, WmsgL, pvp);

        edge_fused<<<ROW_GRID, 256>>>(pkp, pvp, pq, src, etype, poff, peidx,
                                      pri + l * Hh * Rr, pex, pagg);

        typed_gemm_tc<<<TG_GRID, 256>>>(pagg, Wa + l * Tt * Dd * Dd, ntype, pha);

        node_epilogue<<<ROW_GRID, 256>>>(X, pha, ntype, skip + l * Tt,
                                         lng + l * Dd, lnb + l * Dd, OutL);
    }

    final_mix<<<ROW_GRID, 256>>>(po0, po1, aggw, aggg, aggb, out);
}

// round 4
// speedup vs baseline: 4.0878x; 1.2702x over previous
#include <cuda_runtime.h>
#include <cuda_fp16.h>
#include <math.h>

#define Nn 50000
#define Ee 400000
#define Dd 128
#define Hh 4
#define DHh 32
#define Tt 3
#define Rr 6
#define Ll 2

// ---------------- scratch ----------------
__device__ float  g_k[Nn * Dd];
__device__ float  g_q[Nn * Dd];
__device__ float  g_v[Nn * Dd];
__device__ __half g_kp[(long)Rr * Nn * Dd];   // fp16 k' = k @ W_att
__device__ __half g_vp[(long)Rr * Nn * Dd];   // fp16 v' = v @ W_msg
__device__ float  g_agg[Nn * Dd];
__device__ float  g_ha[Nn * Dd];
__device__ float  g_out0[Nn * Dd];
__device__ float  g_out1[Nn * Dd];
__device__ int g_cnt[Nn];
__device__ int g_off[Nn + 1];
__device__ int g_cur[Nn];
__device__ int g_eidx[Ee];

// ---------------- tf32 helpers ----------------
__device__ __forceinline__ unsigned f2tf(float f) {
    unsigned u;
    asm("cvt.rna.tf32.f32 %0, %1;" : "=r"(u) : "f"(f));
    return u;
}

__device__ __forceinline__ void mma8(float c[4], const unsigned a[4],
                                     unsigned b0, unsigned b1) {
    asm volatile(
        "mma.sync.aligned.m16n8k8.row.col.f32.tf32.tf32.f32 "
        "{%0,%1,%2,%3},{%4,%5,%6,%7},{%8,%9},{%0,%1,%2,%3};"
        : "+f"(c[0]), "+f"(c[1]), "+f"(c[2]), "+f"(c[3])
        : "r"(a[0]), "r"(a[1]), "r"(a[2]), "r"(a[3]), "r"(b0), "r"(b1));
}

// ---------------- fused QKV typed GEMM (tf32) ----------------
// One block = 128 rows. X tile (128x128, tf32) loaded/converted ONCE into smem,
// then Wk/Wq/Wv GEMMs run back-to-back. 8 warps: 4(m) x 2(n), warp tile 32x64.
__global__ void qkv_fused_tc(const float* __restrict__ X,
                             const float* __restrict__ Wk_,
                             const float* __restrict__ Wq_,
                             const float* __restrict__ Wv_,
                             const int* __restrict__ ntype,
                             float* __restrict__ Ok, float* __restrict__ Oq,
                             float* __restrict__ Ov) {
    extern __shared__ unsigned sm[];
    unsigned (*Xs)[132] = (unsigned(*)[132])sm;             // [128][132]
    unsigned (*Ws)[132] = (unsigned(*)[132])(sm + 128 * 132); // [32][132]
    __shared__ int ts[128];
    const int r0 = blockIdx.x * 128;
    const int tid = threadIdx.x;

    for (int i = tid; i < 128; i += 256) {
        int row = r0 + i;
        ts[i] = (row < Nn) ? ntype[row] : ntype[Nn - 1];
    }
    __syncthreads();
    const int nrows = (Nn - r0 < 128) ? (Nn - r0) : 128;
    const int t0 = ts[0], t1 = ts[nrows - 1];

    // full X tile: 128 x 128 -> tf32 smem
#pragma unroll
    for (int j = 0; j < 16; ++j) {
        int idx = tid + j * 256;
        int row = idx >> 5, q = idx & 31;
        float4 v = make_float4(0.f, 0.f, 0.f, 0.f);
        if (r0 + row < Nn) v = *(const float4*)(X + (r0 + row) * 128 + q * 4);
        unsigned* d = &Xs[row][q * 4];
        d[0] = f2tf(v.x); d[1] = f2tf(v.y); d[2] = f2tf(v.z); d[3] = f2tf(v.w);
    }

    const int wid = tid >> 5, lane = tid & 31;
    const int gid = lane >> 2, tig = lane & 3;
    const int wm = wid & 3, wn = wid >> 2;

    const float* Wmat[3] = {Wk_, Wq_, Wv_};
    float* Omat[3] = {Ok, Oq, Ov};

#pragma unroll
    for (int m = 0; m < 3; ++m) {
        const float* Wb = Wmat[m];
        float* Out = Omat[m];
        for (int t = t0; t <= t1; ++t) {
            const float* Wt = Wb + t * 16384;
            float c[2][8][4];
#pragma unroll
            for (int mi = 0; mi < 2; ++mi)
#pragma unroll
                for (int ni = 0; ni < 8; ++ni) {
                    c[mi][ni][0] = 0.f; c[mi][ni][1] = 0.f;
                    c[mi][ni][2] = 0.f; c[mi][ni][3] = 0.f;
                }
            for (int kc = 0; kc < 4; ++kc) {
                __syncthreads();
#pragma unroll
                for (int j = 0; j < 4; ++j) {
                    int idx = tid + j * 256;
                    int kr = idx >> 5, q = idx & 31;
                    float4 v = *(const float4*)(Wt + (kc * 32 + kr) * 128 + q * 4);
                    unsigned* d = &Ws[kr][q * 4];
                    d[0] = f2tf(v.x); d[1] = f2tf(v.y); d[2] = f2tf(v.z); d[3] = f2tf(v.w);
                }
                __syncthreads();
#pragma unroll
                for (int ks = 0; ks < 4; ++ks) {
                    int kb = ks * 8;
                    unsigned a[2][4];
#pragma unroll
                    for (int mi = 0; mi < 2; ++mi) {
                        int rl = wm * 32 + mi * 16 + gid;
                        a[mi][0] = Xs[rl][kc * 32 + kb + tig];
                        a[mi][1] = Xs[rl + 8][kc * 32 + kb + tig];
                        a[mi][2] = Xs[rl][kc * 32 + kb + tig + 4];
                        a[mi][3] = Xs[rl + 8][kc * 32 + kb + tig + 4];
                    }
#pragma unroll
                    for (int ni = 0; ni < 8; ++ni) {
                        int cc = wn * 64 + ni * 8 + gid;
                        unsigned b0 = Ws[kb + tig][cc];
                        unsigned b1 = Ws[kb + tig + 4][cc];
                        mma8(c[0][ni], a[0], b0, b1);
                        mma8(c[1][ni], a[1], b0, b1);
                    }
                }
            }
#pragma unroll
            for (int mi = 0; mi < 2; ++mi) {
                int rl = wm * 32 + mi * 16 + gid;
                int rh = rl + 8;
#pragma unroll
                for (int ni = 0; ni < 8; ++ni) {
                    int cc = wn * 64 + ni * 8 + 2 * tig;
                    if (r0 + rl < Nn && ts[rl] == t)
                        *(float2*)(Out + (r0 + rl) * 128 + cc) =
                            make_float2(c[mi][ni][0], c[mi][ni][1]);
                    if (r0 + rh < Nn && ts[rh] == t)
                        *(float2*)(Out + (r0 + rh) * 128 + cc) =
                            make_float2(c[mi][ni][2], c[mi][ni][3]);
                }
            }
        }
    }
}

// ---------------- typed GEMM (tf32), for Wa ----------------
__global__ void typed_gemm_tc(const float* __restrict__ X, const float* __restrict__ W,
                              const int* __restrict__ ntype, float* __restrict__ Out) {
    __shared__ unsigned Xs[128][36];
    __shared__ unsigned Ws[32][132];
    __shared__ int ts[128];
    const int r0 = blockIdx.x * 128;
    const int tid = threadIdx.x;

    for (int i = tid; i < 128; i += 256) {
        int row = r0 + i;
        ts[i] = (row < Nn) ? ntype[row] : ntype[Nn - 1];
    }
    __syncthreads();
    const int nrows = (Nn - r0 < 128) ? (Nn - r0) : 128;
    const int t0 = ts[0], t1 = ts[nrows - 1];

    const int wid = tid >> 5, lane = tid & 31;
    const int gid = lane >> 2, tig = lane & 3;
    const int wm = wid & 3, wn = wid >> 2;

    for (int t = t0; t <= t1; ++t) {
        const float* Wt = W + t * 16384;
        float c[2][8][4];
#pragma unroll
        for (int mi = 0; mi < 2; ++mi)
#pragma unroll
            for (int ni = 0; ni < 8; ++ni) {
                c[mi][ni][0] = 0.f; c[mi][ni][1] = 0.f;
                c[mi][ni][2] = 0.f; c[mi][ni][3] = 0.f;
            }
        for (int kc = 0; kc < 4; ++kc) {
#pragma unroll
            for (int j = 0; j < 4; ++j) {
                int idx = tid + j * 256;
                int row = idx >> 3, q = idx & 7;
                float4 v = make_float4(0.f, 0.f, 0.f, 0.f);
                if (r0 + row < Nn)
                    v = *(const float4*)(X + (r0 + row) * 128 + kc * 32 + q * 4);
                unsigned* d = &Xs[row][q * 4];
                d[0] = f2tf(v.x); d[1] = f2tf(v.y); d[2] = f2tf(v.z); d[3] = f2tf(v.w);
            }
#pragma unroll
            for (int j = 0; j < 4; ++j) {
                int idx = tid + j * 256;
                int kr = idx >> 5, q = idx & 31;
                float4 v = *(const float4*)(W + t * 16384 + (kc * 32 + kr) * 128 + q * 4);
                unsigned* d = &Ws[kr][q * 4];
                d[0] = f2tf(v.x); d[1] = f2tf(v.y); d[2] = f2tf(v.z); d[3] = f2tf(v.w);
            }
            __syncthreads();
#pragma unroll
            for (int ks = 0; ks < 4; ++ks) {
                int kb = ks * 8;
                unsigned a[2][4];
#pragma unroll
                for (int mi = 0; mi < 2; ++mi) {
                    int rl = wm * 32 + mi * 16 + gid;
                    a[mi][0] = Xs[rl][kb + tig];
                    a[mi][1] = Xs[rl + 8][kb + tig];
                    a[mi][2] = Xs[rl][kb + tig + 4];
                    a[mi][3] = Xs[rl + 8][kb + tig + 4];
                }
#pragma unroll
                for (int ni = 0; ni < 8; ++ni) {
                    int cc = wn * 64 + ni * 8 + gid;
                    unsigned b0 = Ws[kb + tig][cc];
                    unsigned b1 = Ws[kb + tig + 4][cc];
                    mma8(c[0][ni], a[0], b0, b1);
                    mma8(c[1][ni], a[1], b0, b1);
                }
            }
            __syncthreads();
        }
#pragma unroll
        for (int mi = 0; mi < 2; ++mi) {
            int rl = wm * 32 + mi * 16 + gid;
            int rh = rl + 8;
#pragma unroll
            for (int ni = 0; ni < 8; ++ni) {
                int cc = wn * 64 + ni * 8 + 2 * tig;
                if (r0 + rl < Nn && ts[rl] == t)
                    *(float2*)(Out + (r0 + rl) * 128 + cc) =
                        make_float2(c[mi][ni][0], c[mi][ni][1]);
                if (r0 + rh < Nn && ts[rh] == t)
                    *(float2*)(Out + (r0 + rh) * 128 + cc) =
                        make_float2(c[mi][ni][2], c[mi][ni][3]);
            }
        }
    }
}

// ---------------- expand (tf32 -> fp16 out) ----------------
// Out[r][n][h*32+o] = sum_d In[n][h*32+d] * W[h][r][d][o], stored as __half
__global__ void expand_tc(const float* __restrict__ In, const float* __restrict__ W,
                          __half* __restrict__ Out) {
    extern __shared__ unsigned sm[];
    unsigned* Xs = sm;               // [64][132]
    unsigned* Wsm = sm + 64 * 132;   // [4][32][36]
    const int r0 = blockIdx.x * 64;
    const int tid = threadIdx.x;
    const int wid = tid >> 5, lane = tid & 31;
    const int gid = lane >> 2, tig = lane & 3;
    const int wm = wid & 1, h = wid >> 1;

#pragma unroll
    for (int j = 0; j < 8; ++j) {
        int idx = tid + j * 256;
        int row = idx >> 5, q = idx & 31;
        float4 v = make_float4(0.f, 0.f, 0.f, 0.f);
        if (r0 + row < Nn)
            v = *(const float4*)(In + (r0 + row) * 128 + q * 4);
        unsigned* d = &Xs[row * 132 + q * 4];
        d[0] = f2tf(v.x); d[1] = f2tf(v.y); d[2] = f2tf(v.z); d[3] = f2tf(v.w);
    }

    for (int r = 0; r < Rr; ++r) {
        __syncthreads();
#pragma unroll
        for (int j = 0; j < 4; ++j) {
            int idx = tid + j * 256;
            int hh = idx >> 8, rem = idx & 255;
            int dd = rem >> 3, q = rem & 7;
            float4 v = *(const float4*)(W + (((hh * Rr + r) * 32 + dd) * 32) + q * 4);
            unsigned* d = &Wsm[(hh * 32 + dd) * 36 + q * 4];
            d[0] = f2tf(v.x); d[1] = f2tf(v.y); d[2] = f2tf(v.z); d[3] = f2tf(v.w);
        }
        __syncthreads();

        float c[2][4][4];
#pragma unroll
        for (int mi = 0; mi < 2; ++mi)
#pragma unroll
            for (int ni = 0; ni < 4; ++ni) {
                c[mi][ni][0] = 0.f; c[mi][ni][1] = 0.f;
                c[mi][ni][2] = 0.f; c[mi][ni][3] = 0.f;
            }
#pragma unroll
        for (int ks = 0; ks < 4; ++ks) {
            int kb = ks * 8;
            unsigned a[2][4];
#pragma unroll
            for (int mi = 0; mi < 2; ++mi) {
                int rl = wm * 32 + mi * 16 + gid;
                int col = h * 32 + kb + tig;
                a[mi][0] = Xs[rl * 132 + col];
                a[mi][1] = Xs[(rl + 8) * 132 + col];
                a[mi][2] = Xs[rl * 132 + col + 4];
                a[mi][3] = Xs[(rl + 8) * 132 + col + 4];
            }
#pragma unroll
            for (int ni = 0; ni < 4; ++ni) {
                int cc = ni * 8 + gid;
                unsigned b0 = Wsm[(h * 32 + kb + tig) * 36 + cc];
                unsigned b1 = Wsm[(h * 32 + kb + tig + 4) * 36 + cc];
                mma8(c[0][ni], a[0], b0, b1);
                mma8(c[1][ni], a[1], b0, b1);
            }
        }
#pragma unroll
        for (int mi = 0; mi < 2; ++mi) {
            int rl = wm * 32 + mi * 16 + gid;
            int rh = rl + 8;
#pragma unroll
            for (int ni = 0; ni < 4; ++ni) {
                int cc = h * 32 + ni * 8 + 2 * tig;
                if (r0 + rl < Nn)
                    *(__half2*)(Out + ((long)r * Nn + r0 + rl) * 128 + cc) =
                        __floats2half2_rn(c[mi][ni][0], c[mi][ni][1]);
                if (r0 + rh < Nn)
                    *(__half2*)(Out + ((long)r * Nn + r0 + rh) * 128 + cc) =
                        __floats2half2_rn(c[mi][ni][2], c[mi][ni][3]);
            }
        }
    }
}

// ---------------- CSR build ----------------
__global__ void hist_dst(const int* __restrict__ dst, int* __restrict__ cnt) {
    for (int e = blockIdx.x * blockDim.x + threadIdx.x; e < Ee; e += gridDim.x * blockDim.x)
        atomicAdd(&cnt[dst[e]], 1);
}

__global__ void scan_offsets(const int* __restrict__ cnt, int* __restrict__ off) {
    __shared__ int wsum[32];
    __shared__ int carry;
    const int lane = threadIdx.x & 31;
    const int w = threadIdx.x >> 5;
    if (threadIdx.x == 0) { carry = 0; off[0] = 0; }
    __syncthreads();
    for (int base = 0; base < Nn; base += 1024) {
        int i = base + threadIdx.x;
        int x = (i < Nn) ? cnt[i] : 0;
#pragma unroll
        for (int o = 1; o < 32; o <<= 1) {
            int t = __shfl_up_sync(0xffffffffu, x, o);
            if (lane >= o) x += t;
        }
        if (lane == 31) wsum[w] = x;
        __syncthreads();
        if (w == 0) {
            int s = wsum[lane];
#pragma unroll
            for (int o = 1; o < 32; o <<= 1) {
                int t = __shfl_up_sync(0xffffffffu, s, o);
                if (lane >= o) s += t;
            }
            wsum[lane] = s;
        }
        __syncthreads();
        int incl = x + (w > 0 ? wsum[w - 1] : 0) + carry;
        if (i < Nn) off[i + 1] = incl;
        __syncthreads();
        if (threadIdx.x == 1023) carry = incl;
        __syncthreads();
    }
}

__global__ void scatter_edges(const int* __restrict__ dst, int* __restrict__ cur,
                              int* __restrict__ eidx) {
    for (int e = blockIdx.x * blockDim.x + threadIdx.x; e < Ee; e += gridDim.x * blockDim.x) {
        int p = atomicAdd(&cur[dst[e]], 1);
        eidx[p] = e;
    }
}

// ---------------- single-pass fused edge kernel: warp per dst node ----------------
// acc = sum_e exp(a_e) * v'_e ; den = sum_e exp(a_e) ; agg = acc/den. No ex array.
__global__ void edge_fused(const __half* __restrict__ kp, const __half* __restrict__ vp,
                           const float* __restrict__ qq,
                           const int* __restrict__ src, const int* __restrict__ etype,
                           const int* __restrict__ off, const int* __restrict__ eidx,
                           const float* __restrict__ pri,
                           float* __restrict__ agg) {
    __shared__ float Pri[Hh * Rr];
    if (threadIdx.x < Hh * Rr) Pri[threadIdx.x] = pri[threadIdx.x];
    __syncthreads();

    const int lane = threadIdx.x & 31;
    const int n = blockIdx.x * (blockDim.x >> 5) + (threadIdx.x >> 5);
    if (n >= Nn) return;
    const int h = lane >> 3;
    const int beg = off[n], end = off[n + 1];

    float4 q4 = ((const float4*)(qq + n * Dd))[lane];
    float den = 0.f;
    float4 acc = make_float4(0.f, 0.f, 0.f, 0.f);
    for (int i = beg; i < end; ++i) {
        int e = eidx[i];
        int s = src[e], r = etype[e];
        long base = ((long)r * Nn + s) * 128;
        uint2 ku = ((const uint2*)(kp + base))[lane];
        uint2 vu = ((const uint2*)(vp + base))[lane];
        float2 k0 = __half22float2(*(__half2*)&ku.x);
        float2 k1 = __half22float2(*(__half2*)&ku.y);
        float p = k0.x * q4.x + k0.y * q4.y + k1.x * q4.z + k1.y * q4.w;
        p += __shfl_xor_sync(0xffffffffu, p, 1);
        p += __shfl_xor_sync(0xffffffffu, p, 2);
        p += __shfl_xor_sync(0xffffffffu, p, 4);
        float ev = expf(p * Pri[h * Rr + r] * 0.17677669529663687f);
        den += ev;
        float2 v0 = __half22float2(*(__half2*)&vu.x);
        float2 v1 = __half22float2(*(__half2*)&vu.y);
        acc.x += ev * v0.x;
        acc.y += ev * v0.y;
        acc.z += ev * v1.x;
        acc.w += ev * v1.y;
    }
    float invd = (den > 0.f) ? (1.f / den) : 0.f;
    acc.x *= invd; acc.y *= invd; acc.z *= invd; acc.w *= invd;
    ((float4*)agg)[n * 32 + lane] = acc;
}

// ---------------- per-node epilogue ----------------
__global__ void node_epilogue(const float* __restrict__ X, const float* __restrict__ Ha,
                              const int* __restrict__ ntype,
                              const float* __restrict__ skip,
                              const float* __restrict__ lng, const float* __restrict__ lnb,
                              float* __restrict__ OutL) {
    const int lane = threadIdx.x & 31;
    const int row = blockIdx.x * (blockDim.x >> 5) + (threadIdx.x >> 5);
    if (row >= Nn) return;
    int t = ntype[row];
    float sk = 1.f / (1.f + expf(-skip[t]));

    float4 x4 = ((const float4*)X)[row * 32 + lane];
    float4 h4 = ((const float4*)Ha)[row * 32 + lane];
    float p0 = x4.x * (2.f - sk) + h4.x * sk;
    float p1 = x4.y * (2.f - sk) + h4.y * sk;
    float p2 = x4.z * (2.f - sk) + h4.z * sk;
    float p3 = x4.w * (2.f - sk) + h4.w * sk;

    float s = p0 + p1 + p2 + p3;
#pragma unroll
    for (int off = 16; off > 0; off >>= 1) s += __shfl_xor_sync(0xffffffffu, s, off);
    float mu = s * (1.f / 128.f);
    float d0 = p0 - mu, d1 = p1 - mu, d2 = p2 - mu, d3 = p3 - mu;
    float qv = d0 * d0 + d1 * d1 + d2 * d2 + d3 * d3;
#pragma unroll
    for (int off = 16; off > 0; off >>= 1) qv += __shfl_xor_sync(0xffffffffu, qv, off);
    float inv = rsqrtf(qv * (1.f / 128.f) + 1e-5f);

    float4 g4 = ((const float4*)lng)[lane];
    float4 b4 = ((const float4*)lnb)[lane];
    float4 o;
    o.x = d0 * inv * g4.x + b4.x;
    o.y = d1 * inv * g4.y + b4.y;
    o.z = d2 * inv * g4.z + b4.z;
    o.w = d3 * inv * g4.w + b4.w;
    ((float4*)OutL)[row * 32 + lane] = o;
}

// ---------------- final mix + LN ----------------
__global__ void final_mix(const float* __restrict__ o0, const float* __restrict__ o1,
                          const float* __restrict__ aw,
                          const float* __restrict__ gg, const float* __restrict__ bb,
                          float* __restrict__ out) {
    const int lane = threadIdx.x & 31;
    const int row = blockIdx.x * (blockDim.x >> 5) + (threadIdx.x >> 5);
    if (row >= Nn) return;
    float e0 = expf(aw[0]), e1 = expf(aw[1]);
    float w0 = e0 / (e0 + e1), w1 = e1 / (e0 + e1);

    float4 a4 = ((const float4*)o0)[row * 32 + lane];
    float4 c4 = ((const float4*)o1)[row * 32 + lane];
    float p0 = w0 * a4.x + w1 * c4.x;
    float p1 = w0 * a4.y + w1 * c4.y;
    float p2 = w0 * a4.z + w1 * c4.z;
    float p3 = w0 * a4.w + w1 * c4.w;

    float s = p0 + p1 + p2 + p3;
#pragma unroll
    for (int off = 16; off > 0; off >>= 1) s += __shfl_xor_sync(0xffffffffu, s, off);
    float mu = s * (1.f / 128.f);
    float d0 = p0 - mu, d1 = p1 - mu, d2 = p2 - mu, d3 = p3 - mu;
    float qv = d0 * d0 + d1 * d1 + d2 * d2 + d3 * d3;
#pragma unroll
    for (int off = 16; off > 0; off >>= 1) qv += __shfl_xor_sync(0xffffffffu, qv, off);
    float inv = rsqrtf(qv * (1.f / 128.f) + 1e-5f);

    float4 g4 = ((const float4*)gg)[lane];
    float4 b4 = ((const float4*)bb)[lane];
    float4 o;
    o.x = d0 * inv * g4.x + b4.x;
    o.y = d1 * inv * g4.y + b4.y;
    o.z = d2 * inv * g4.z + b4.z;
    o.w = d3 * inv * g4.w + b4.w;
    ((float4*)out)[row * 32 + lane] = o;
}

extern "C" void kernel_launch(void* const* d_in, const int* in_sizes, int n_in,
                              void* d_out, int out_size) {
    (void)in_sizes; (void)n_in; (void)out_size;
    const float* h     = (const float*)d_in[0];
    const int*   src   = (const int*)d_in[1];
    const int*   dst   = (const int*)d_in[2];
    const int*   ntype = (const int*)d_in[3];
    const int*   etype = (const int*)d_in[4];
    const float* Wk    = (const float*)d_in[5];
    const float* Wq    = (const float*)d_in[6];
    const float* Wv    = (const float*)d_in[7];
    const float* Wa    = (const float*)d_in[8];
    const float* Watt  = (const float*)d_in[9];
    const float* Wmsg  = (const float*)d_in[10];
    const float* pri   = (const float*)d_in[11];
    const float* skip  = (const float*)d_in[12];
    const float* lng   = (const float*)d_in[13];
    const float* lnb   = (const float*)d_in[14];
    const float* aggw  = (const float*)d_in[15];
    const float* aggg  = (const float*)d_in[16];
    const float* aggb  = (const float*)d_in[17];
    float* out = (float*)d_out;

    float *pk, *pq, *pv, *pagg, *pha, *po0, *po1;
    __half *pkp, *pvp;
    int *pcnt, *poff, *pcur, *peidx;
    cudaGetSymbolAddress((void**)&pk,   g_k);
    cudaGetSymbolAddress((void**)&pq,   g_q);
    cudaGetSymbolAddress((void**)&pv,   g_v);
    cudaGetSymbolAddress((void**)&pkp,  g_kp);
    cudaGetSymbolAddress((void**)&pvp,  g_vp);
    cudaGetSymbolAddress((void**)&pagg, g_agg);
    cudaGetSymbolAddress((void**)&pha,  g_ha);
    cudaGetSymbolAddress((void**)&po0,  g_out0);
    cudaGetSymbolAddress((void**)&po1,  g_out1);
    cudaGetSymbolAddress((void**)&pcnt, g_cnt);
    cudaGetSymbolAddress((void**)&poff, g_off);
    cudaGetSymbolAddress((void**)&pcur, g_cur);
    cudaGetSymbolAddress((void**)&peidx, g_eidx);

    const int QKV_SMEM = (128 * 132 + 32 * 132) * (int)sizeof(unsigned);  // 84480
    const int EXP_SMEM = (64 * 132 + 4 * 32 * 36) * (int)sizeof(unsigned); // 52224
    cudaFuncSetAttribute(qkv_fused_tc, cudaFuncAttributeMaxDynamicSharedMemorySize, QKV_SMEM);
    cudaFuncSetAttribute(expand_tc, cudaFuncAttributeMaxDynamicSharedMemorySize, EXP_SMEM);

    const int TG_GRID  = (Nn + 127) / 128;  // 391
    const int EX_GRID  = (Nn + 63) / 64;    // 782
    const int ROW_GRID = (Nn + 7) / 8;      // 6250
    const int EGRID    = 592;

    // ---- CSR by dst (graph static across layers) ----
    cudaMemsetAsync(pcnt, 0, Nn * sizeof(int), 0);
    hist_dst<<<EGRID, 256>>>(dst, pcnt);
    scan_offsets<<<1, 1024>>>(pcnt, poff);
    cudaMemcpyAsync(pcur, poff, Nn * sizeof(int), cudaMemcpyDeviceToDevice, 0);
    scatter_edges<<<EGRID, 256>>>(dst, pcur, peidx);

    for (int l = 0; l < Ll; ++l) {
        const float* X = (l == 0) ? h : po0;
        float* OutL = (l == 0) ? po0 : po1;
        const float* WattL = Watt + l * Hh * Rr * DHh * DHh;
        const float* WmsgL = Wmsg + l * Hh * Rr * DHh * DHh;

        qkv_fused_tc<<<TG_GRID, 256, QKV_SMEM>>>(X, Wk + l * Tt * Dd * Dd,
                                                 Wq + l * Tt * Dd * Dd,
                                                 Wv + l * Tt * Dd * Dd,
                                                 ntype, pk, pq, pv);

        expand_tc<<<EX_GRID, 256, EXP_SMEM>>>(pk, WattL, pkp);
        expand_tc<<<EX_GRID, 256, EXP_SMEM>>>(pv, WmsgL, pvp);

        edge_fused<<<ROW_GRID, 256>>>(pkp, pvp, pq, src, etype, poff, peidx,
                                      pri + l * Hh * Rr, pagg);

        typed_gemm_tc<<<TG_GRID, 256>>>(pagg, Wa + l * Tt * Dd * Dd, ntype, pha);

        node_epilogue<<<ROW_GRID, 256>>>(X, pha, ntype, skip + l * Tt,
                                         lng + l * Dd, lnb + l * Dd, OutL);
    }

    final_mix<<<ROW_GRID, 256>>>(po0, po1, aggw, aggg, aggb, out);
}